// round 5
// baseline (speedup 1.0000x reference)
#include <cuda_runtime.h>
#include <cuda_bf16.h>
#include <math.h>

// ---------------------------------------------------------------------------
// Problem constants
// ---------------------------------------------------------------------------
#define N_NODES 8000
#define N_EDGES 64000
#define NBATCH  64
#define NGRID   12
#define HID     128
#define BAS     128
#define NLAYERS 3
#define IN_S    16
#define IN_V    2
#define OUT_S   8
#define OUT_V   1
#define WIDE    4

#define R_E (N_EDGES * NGRID)   // 768000 edge-grid rows
#define R_N (N_NODES * NGRID)   // 96000  node-grid rows

// ---------------------------------------------------------------------------
// Device scratch (static __device__ globals -- the allowed scratch mechanism)
// ---------------------------------------------------------------------------
__device__ float g_grid0[NGRID * 3];
__device__ float g_node_grid[R_N * 3];
__device__ float g_kb_sh[144 * HID];
__device__ float g_fk[NLAYERS * 144 * HID];
__device__ float g_poly[R_E * 14];
__device__ float g_buf1[R_E * HID];    // kb_sp hidden; later reused as MLP hidden (96000x512)
__device__ float g_kb_sp[R_E * HID];
__device__ float g_h[R_N * HID];
__device__ float g_agg[R_N * HID];
__device__ float g_hn[R_N * HID];
__device__ float g_readout[R_N * (OUT_S + OUT_V)];

__device__ __forceinline__ float gelu_f(float x) {
    return 0.5f * x * (1.0f + erff(x * 0.70710678118654752440f));
}

// ---------------------------------------------------------------------------
// Setup kernels
// ---------------------------------------------------------------------------
__global__ void grid0_kernel() {
    int i = threadIdx.x;
    if (i < NGRID) {
        const float golden = 1.61803398874989484820f;
        float fi = (float)i;
        float theta = 6.28318530717958647692f * fi / golden;
        float z = 1.0f - (2.0f * fi + 1.0f) / (float)NGRID;
        float r = sqrtf(fmaxf(1.0f - z * z, 0.0f));
        g_grid0[i * 3 + 0] = r * cosf(theta);
        g_grid0[i * 3 + 1] = r * sinf(theta);
        g_grid0[i * 3 + 2] = z;
    }
}

// kb_sh: 144 rows (p,o), MLP 3 -> 128 (gelu) -> 128 (gelu)
__global__ void kbsh_kernel(const float* __restrict__ Wsh1, const float* __restrict__ bsh1,
                            const float* __restrict__ Wsh2, const float* __restrict__ bsh2) {
    int row = blockIdx.x;           // p*12 + o
    int p = row / NGRID, o = row % NGRID;
    int c = threadIdx.x;            // 128
    __shared__ float h1[HID];
    float t = g_grid0[p*3+0]*g_grid0[o*3+0] + g_grid0[p*3+1]*g_grid0[o*3+1] + g_grid0[p*3+2]*g_grid0[o*3+2];
    float t2 = t * t, t3 = t2 * t;
    float v = t * Wsh1[c] + t2 * Wsh1[HID + c] + t3 * Wsh1[2*HID + c] + bsh1[c];
    h1[c] = gelu_f(v);
    __syncthreads();
    float acc = bsh2[c];
    #pragma unroll 8
    for (int k = 0; k < HID; k++) acc = fmaf(h1[k], Wsh2[k*HID + c], acc);
    g_kb_sh[row * HID + c] = gelu_f(acc);
}

// fk[l] = kb_sh @ Wfk[l]  (3 * 144 rows)
__global__ void fk_kernel(const float* __restrict__ Wfk) {
    int blk = blockIdx.x;
    int l = blk / 144, row = blk % 144;
    int c = threadIdx.x;
    __shared__ float r128[HID];
    r128[c] = g_kb_sh[row * HID + c];
    __syncthreads();
    const float* W = Wfk + l * HID * HID;
    float acc = 0.0f;
    #pragma unroll 8
    for (int k = 0; k < HID; k++) acc = fmaf(r128[k], W[k*HID + c], acc);
    g_fk[l * 144 * HID + row * HID + c] = acc;
}

// node_grid + initial embedding h0 = f @ Wemb
__global__ void embed_kernel(const float* __restrict__ x, const float* __restrict__ vec,
                             const float* __restrict__ Q, const int* __restrict__ batch,
                             const float* __restrict__ Wemb) {
    int v = blockIdx.x;
    int c = threadIdx.x;  // 128
    __shared__ float sQ[9], sx[IN_S], sv[6], sng[NGRID * 3];
    int b = batch[v];
    if (c < 9)  sQ[c] = Q[b * 9 + c];
    if (c < IN_S) sx[c] = x[v * IN_S + c];
    if (c < 6)  sv[c] = vec[v * 6 + c];
    __syncthreads();
    if (c < NGRID * 3) {
        int n = c / 3, i = c % 3;
        float t = sQ[i*3+0]*g_grid0[n*3+0] + sQ[i*3+1]*g_grid0[n*3+1] + sQ[i*3+2]*g_grid0[n*3+2];
        sng[c] = t;
        g_node_grid[v * NGRID * 3 + c] = t;
    }
    __syncthreads();
    float s = 0.0f;
    #pragma unroll
    for (int j = 0; j < IN_S; j++) s = fmaf(sx[j], Wemb[j * HID + c], s);
    float w16 = Wemb[IN_S * HID + c];
    float w17 = Wemb[(IN_S + 1) * HID + c];
    #pragma unroll
    for (int n = 0; n < NGRID; n++) {
        float xv0 = sv[0]*sng[n*3+0] + sv[1]*sng[n*3+1] + sv[2]*sng[n*3+2];
        float xv1 = sv[3]*sng[n*3+0] + sv[4]*sng[n*3+1] + sv[5]*sng[n*3+2];
        g_h[(v * NGRID + n) * HID + c] = s + xv0 * w16 + xv1 * w17;
    }
}

// attr_sp -> degree-3 poly features (14), per edge-grid row
__global__ void poly_kernel(const float* __restrict__ pos,
                            const int* __restrict__ send, const int* __restrict__ recv) {
    int r = blockIdx.x * 256 + threadIdx.x;
    if (r >= R_E) return;
    int e = r / NGRID, o = r % NGRID;
    int s = send[e], rc = recv[e];
    float rx = pos[s*3+0] - pos[rc*3+0];
    float ry = pos[s*3+1] - pos[rc*3+1];
    float rz = pos[s*3+2] - pos[rc*3+2];
    const float* g = &g_node_grid[(rc * NGRID + o) * 3];
    float g0 = g[0], g1 = g[1], g2 = g[2];
    float inv1 = rx*g0 + ry*g1 + rz*g2;
    float dx = rx - inv1*g0, dy = ry - inv1*g1, dz = rz - inv1*g2;
    float inv2 = sqrtf(dx*dx + dy*dy + dz*dz);
    float* p = &g_poly[(size_t)r * 14];
    float a = inv1, b = inv2;
    p[0]=a; p[1]=b;
    p[2]=a*a; p[3]=a*b; p[4]=b*a; p[5]=b*b;
    p[6]=p[2]*a; p[7]=p[2]*b; p[8]=p[3]*a; p[9]=p[3]*b;
    p[10]=p[4]*a; p[11]=p[4]*b; p[12]=p[5]*a; p[13]=p[5]*b;
}

// ---------------------------------------------------------------------------
// Generic fp32 GEMM: C[M,N] = epilogue(A[M,K] @ B[K,N] + bias)
// BM=BN=128, BK=8, 256 threads, 8x8 per thread. M%128==0, N%128==0 assumed.
// MODE: 0 = bias, 1 = bias+gelu, 2 = bias + add addsrc
// ---------------------------------------------------------------------------
template<int MODE>
__global__ __launch_bounds__(256)
void sgemm_kernel(const float* __restrict__ A, const float* __restrict__ Bm,
                  const float* __restrict__ bias, const float* __restrict__ addsrc,
                  float* __restrict__ C, int M, int N, int K) {
    __shared__ __align__(16) float As[8][128];
    __shared__ __align__(16) float Bs[8][128];
    int tid = threadIdx.x;
    int row0 = blockIdx.y * 128;
    int col0 = blockIdx.x * 128;
    int tr = (tid / 16) * 8;
    int tc = (tid % 16) * 8;
    float acc[8][8];
    #pragma unroll
    for (int i = 0; i < 8; i++)
        #pragma unroll
        for (int j = 0; j < 8; j++) acc[i][j] = 0.0f;

    for (int k0 = 0; k0 < K; k0 += 8) {
        #pragma unroll
        for (int i = tid; i < 128 * 8; i += 256) {
            int m = i >> 3, kk = i & 7;
            int k = k0 + kk;
            As[kk][m] = (k < K) ? A[(size_t)(row0 + m) * K + k] : 0.0f;
        }
        #pragma unroll
        for (int i = tid; i < 8 * 128; i += 256) {
            int kk = i >> 7, n = i & 127;
            int k = k0 + kk;
            Bs[kk][n] = (k < K) ? Bm[(size_t)k * N + col0 + n] : 0.0f;
        }
        __syncthreads();
        #pragma unroll
        for (int kk = 0; kk < 8; kk++) {
            float4 a0 = *reinterpret_cast<const float4*>(&As[kk][tr]);
            float4 a1 = *reinterpret_cast<const float4*>(&As[kk][tr + 4]);
            float4 b0 = *reinterpret_cast<const float4*>(&Bs[kk][tc]);
            float4 b1 = *reinterpret_cast<const float4*>(&Bs[kk][tc + 4]);
            float a[8] = {a0.x,a0.y,a0.z,a0.w,a1.x,a1.y,a1.z,a1.w};
            float b[8] = {b0.x,b0.y,b0.z,b0.w,b1.x,b1.y,b1.z,b1.w};
            #pragma unroll
            for (int i = 0; i < 8; i++)
                #pragma unroll
                for (int j = 0; j < 8; j++) acc[i][j] = fmaf(a[i], b[j], acc[i][j]);
        }
        __syncthreads();
    }
    #pragma unroll
    for (int i = 0; i < 8; i++) {
        int r = row0 + tr + i;
        #pragma unroll
        for (int j = 0; j < 8; j++) {
            int cc = col0 + tc + j;
            float v = acc[i][j] + bias[cc];
            if (MODE == 1) v = gelu_f(v);
            if (MODE == 2) v += addsrc[(size_t)r * N + cc];
            C[(size_t)r * N + cc] = v;
        }
    }
}

// ---------------------------------------------------------------------------
// Fused: k = kb_sp @ Wk[l]; msg = h[send]*k; atomicAdd agg[recv]
// M = R_E (div by 128), K = N = 128.
// ---------------------------------------------------------------------------
__global__ __launch_bounds__(256)
void kconv_kernel(const float* __restrict__ kb, const float* __restrict__ Wk,
                  const float* __restrict__ h, float* __restrict__ agg,
                  const int* __restrict__ send, const int* __restrict__ recv) {
    __shared__ __align__(16) float As[8][128];
    __shared__ __align__(16) float Bs[8][128];
    __shared__ int hrow[128], arow[128];
    int tid = threadIdx.x;
    int row0 = blockIdx.x * 128;
    int tr = (tid / 16) * 8;
    int tc = (tid % 16) * 8;
    if (tid < 128) {
        int r = row0 + tid;
        int e = r / NGRID, o = r % NGRID;
        hrow[tid] = send[e] * NGRID + o;
        arow[tid] = recv[e] * NGRID + o;
    }
    float acc[8][8];
    #pragma unroll
    for (int i = 0; i < 8; i++)
        #pragma unroll
        for (int j = 0; j < 8; j++) acc[i][j] = 0.0f;

    for (int k0 = 0; k0 < 128; k0 += 8) {
        #pragma unroll
        for (int i = tid; i < 128 * 8; i += 256) {
            int m = i >> 3, kk = i & 7;
            As[kk][m] = kb[(size_t)(row0 + m) * 128 + k0 + kk];
        }
        #pragma unroll
        for (int i = tid; i < 8 * 128; i += 256) {
            int kk = i >> 7, n = i & 127;
            Bs[kk][n] = Wk[(k0 + kk) * 128 + n];
        }
        __syncthreads();
        #pragma unroll
        for (int kk = 0; kk < 8; kk++) {
            float4 a0 = *reinterpret_cast<const float4*>(&As[kk][tr]);
            float4 a1 = *reinterpret_cast<const float4*>(&As[kk][tr + 4]);
            float4 b0 = *reinterpret_cast<const float4*>(&Bs[kk][tc]);
            float4 b1 = *reinterpret_cast<const float4*>(&Bs[kk][tc + 4]);
            float a[8] = {a0.x,a0.y,a0.z,a0.w,a1.x,a1.y,a1.z,a1.w};
            float b[8] = {b0.x,b0.y,b0.z,b0.w,b1.x,b1.y,b1.z,b1.w};
            #pragma unroll
            for (int i = 0; i < 8; i++)
                #pragma unroll
                for (int j = 0; j < 8; j++) acc[i][j] = fmaf(a[i], b[j], acc[i][j]);
        }
        __syncthreads();
    }
    #pragma unroll
    for (int i = 0; i < 8; i++) {
        int hb = hrow[tr + i] * 128 + tc;
        int ab = arow[tr + i] * 128 + tc;
        float4 h0 = *reinterpret_cast<const float4*>(&h[hb]);
        float4 h1 = *reinterpret_cast<const float4*>(&h[hb + 4]);
        float hv[8] = {h0.x,h0.y,h0.z,h0.w,h1.x,h1.y,h1.z,h1.w};
        #pragma unroll
        for (int j = 0; j < 8; j++) {
            atomicAdd(&agg[ab + j], acc[i][j] * hv[j]);
        }
    }
}

// ---------------------------------------------------------------------------
// x2 = einsum('boc,poc->bpc', agg, fk)/NGRID + bconv ; LayerNorm -> hn
// one block per node, 128 threads (channel)
// ---------------------------------------------------------------------------
__global__ void conv_ln_kernel(const float* __restrict__ agg, const float* __restrict__ fk,
                               const float* __restrict__ bconv, const float* __restrict__ lng,
                               const float* __restrict__ lnb, float* __restrict__ hn) {
    int v = blockIdx.x;
    int c = threadIdx.x;
    float a[NGRID];
    #pragma unroll
    for (int o = 0; o < NGRID; o++) a[o] = agg[(v * NGRID + o) * HID + c];
    __shared__ float warp_red[4];
    __shared__ float bc_val;
    int lane = c & 31, wid = c >> 5;
    float gc = lng[c], bbc = lnb[c], bcv = bconv[c];
    for (int p = 0; p < NGRID; p++) {
        float s = 0.0f;
        #pragma unroll
        for (int o = 0; o < NGRID; o++) s = fmaf(a[o], fk[(p * NGRID + o) * HID + c], s);
        s = s * (1.0f / (float)NGRID) + bcv;
        // mean
        float t = s;
        #pragma unroll
        for (int off = 16; off > 0; off >>= 1) t += __shfl_xor_sync(0xffffffffu, t, off);
        if (lane == 0) warp_red[wid] = t;
        __syncthreads();
        if (c == 0) bc_val = (warp_red[0] + warp_red[1] + warp_red[2] + warp_red[3]) * (1.0f / HID);
        __syncthreads();
        float mu = bc_val;
        float d = s - mu;
        t = d * d;
        #pragma unroll
        for (int off = 16; off > 0; off >>= 1) t += __shfl_xor_sync(0xffffffffu, t, off);
        if (lane == 0) warp_red[wid] = t;
        __syncthreads();
        if (c == 0) bc_val = rsqrtf((warp_red[0] + warp_red[1] + warp_red[2] + warp_red[3]) * (1.0f / HID) + 1e-5f);
        __syncthreads();
        float rstd = bc_val;
        hn[(v * NGRID + p) * HID + c] = d * rstd * gc + bbc;
        __syncthreads();
    }
}

// ---------------------------------------------------------------------------
// readout += (h @ Wro[l] + bro[l]) / L
// 16 rows per block, 160 threads (144 active in compute)
// ---------------------------------------------------------------------------
__global__ void readout_kernel(const float* __restrict__ h, const float* __restrict__ Wro,
                               const float* __restrict__ bro, float* __restrict__ ro) {
    __shared__ float hs[16 * 129];
    int tid = threadIdx.x;
    int r0 = blockIdx.x * 16;
    for (int i = tid; i < 16 * 128; i += 160) {
        int row = i >> 7, cc = i & 127;
        hs[row * 129 + cc] = h[(size_t)(r0 + row) * HID + cc];
    }
    __syncthreads();
    if (tid < 16 * 9) {
        int row = tid / 9, oc = tid % 9;
        float acc = bro[oc];
        #pragma unroll 8
        for (int cc = 0; cc < 128; cc++) acc = fmaf(hs[row * 129 + cc], Wro[cc * 9 + oc], acc);
        int idx = (r0 + row) * 9 + oc;
        ro[idx] += acc * (1.0f / (float)NLAYERS);
    }
}

// ---------------------------------------------------------------------------
// Final pooling: out_s[B,8], out_v[B,1,3]
// ---------------------------------------------------------------------------
__global__ void finalize_kernel(const int* __restrict__ batch, float* __restrict__ out) {
    int v = blockIdx.x * 256 + threadIdx.x;
    if (v >= N_NODES) return;
    float ssum[OUT_S] = {0,0,0,0,0,0,0,0};
    float vsum[3] = {0,0,0};
    for (int n = 0; n < NGRID; n++) {
        const float* rr = &g_readout[(v * NGRID + n) * 9];
        #pragma unroll
        for (int j = 0; j < OUT_S; j++) ssum[j] += rr[j];
        float rv = rr[OUT_S];
        const float* g = &g_node_grid[(v * NGRID + n) * 3];
        vsum[0] += rv * g[0]; vsum[1] += rv * g[1]; vsum[2] += rv * g[2];
    }
    int b = batch[v];
    #pragma unroll
    for (int j = 0; j < OUT_S; j++) atomicAdd(&out[b * OUT_S + j], ssum[j] * (1.0f / NGRID));
    #pragma unroll
    for (int d = 0; d < 3; d++) atomicAdd(&out[NBATCH * OUT_S + b * 3 + d], vsum[d] * (1.0f / NGRID));
}

// grid-stride zeroing (robust to any grid size)
__global__ void zero_kernel(float* __restrict__ p, int n) {
    for (int i = blockIdx.x * blockDim.x + threadIdx.x; i < n; i += gridDim.x * blockDim.x)
        p[i] = 0.0f;
}

__global__ void zero_sym_kernel(int which) {
    // which 0: g_agg, 1: g_readout
    int stride = gridDim.x * blockDim.x;
    if (which == 0) {
        for (int i = blockIdx.x * blockDim.x + threadIdx.x; i < R_N * HID; i += stride) g_agg[i] = 0.0f;
    } else {
        for (int i = blockIdx.x * blockDim.x + threadIdx.x; i < R_N * 9; i += stride) g_readout[i] = 0.0f;
    }
}

// ---------------------------------------------------------------------------
// Host launcher
// ---------------------------------------------------------------------------
extern "C" void kernel_launch(void* const* d_in, const int* in_sizes, int n_in,
                              void* d_out, int out_size) {
    const float* x      = (const float*)d_in[0];
    const float* vec    = (const float*)d_in[1];
    const float* pos    = (const float*)d_in[2];
    const float* Q      = (const float*)d_in[3];
    const float* Wsp1   = (const float*)d_in[4];
    const float* bsp1   = (const float*)d_in[5];
    const float* Wsp2   = (const float*)d_in[6];
    const float* bsp2   = (const float*)d_in[7];
    const float* Wsh1   = (const float*)d_in[8];
    const float* bsh1   = (const float*)d_in[9];
    const float* Wsh2   = (const float*)d_in[10];
    const float* bsh2   = (const float*)d_in[11];
    const float* Wemb   = (const float*)d_in[12];
    const float* Wk     = (const float*)d_in[13];
    const float* Wfk    = (const float*)d_in[14];
    const float* bconv  = (const float*)d_in[15];
    const float* ln_g   = (const float*)d_in[16];
    const float* ln_b   = (const float*)d_in[17];
    const float* W1     = (const float*)d_in[18];
    const float* b1     = (const float*)d_in[19];
    const float* W2     = (const float*)d_in[20];
    const float* b2     = (const float*)d_in[21];
    const float* Wro    = (const float*)d_in[22];
    const float* bro    = (const float*)d_in[23];
    const int*   eidx   = (const int*)d_in[24];
    const int*   batch  = (const int*)d_in[25];
    float* out = (float*)d_out;

    const int* send = eidx;
    const int* recv = eidx + N_EDGES;

    // resolve device-symbol addresses (host-side lookup; not an allocation)
    float *p_poly, *p_buf1, *p_kb_sp, *p_h, *p_agg, *p_hn, *p_readout, *p_fk;
    cudaGetSymbolAddress((void**)&p_poly,   g_poly);
    cudaGetSymbolAddress((void**)&p_buf1,   g_buf1);
    cudaGetSymbolAddress((void**)&p_kb_sp,  g_kb_sp);
    cudaGetSymbolAddress((void**)&p_h,      g_h);
    cudaGetSymbolAddress((void**)&p_agg,    g_agg);
    cudaGetSymbolAddress((void**)&p_hn,     g_hn);
    cudaGetSymbolAddress((void**)&p_readout,g_readout);
    cudaGetSymbolAddress((void**)&p_fk,     g_fk);

    // setup
    grid0_kernel<<<1, 32>>>();
    kbsh_kernel<<<144, 128>>>(Wsh1, bsh1, Wsh2, bsh2);
    fk_kernel<<<NLAYERS * 144, 128>>>(Wfk);
    embed_kernel<<<N_NODES, 128>>>(x, vec, Q, batch, Wemb);
    poly_kernel<<<(R_E + 255) / 256, 256>>>(pos, send, recv);

    // kb_sp MLP: [R_E x 14] -> 128 (gelu) -> 128 (gelu)
    sgemm_kernel<1><<<dim3(1, R_E / 128), 256>>>(p_poly, Wsp1, bsp1, nullptr, p_buf1, R_E, 128, 14);
    sgemm_kernel<1><<<dim3(1, R_E / 128), 256>>>(p_buf1, Wsp2, bsp2, nullptr, p_kb_sp, R_E, 128, 128);

    zero_sym_kernel<<<1024, 256>>>(1);

    for (int l = 0; l < NLAYERS; l++) {
        zero_sym_kernel<<<4096, 256>>>(0);
        kconv_kernel<<<R_E / 128, 256>>>(p_kb_sp, Wk + l * HID * HID, p_h, p_agg, send, recv);
        conv_ln_kernel<<<N_NODES, 128>>>(p_agg, p_fk + l * 144 * HID,
                                         bconv + l * HID, ln_g + l * HID, ln_b + l * HID, p_hn);
        // MLP: hn @ W1 (128->512) gelu -> buf1 ; buf1 @ W2 (512->128) + b2 + h -> h
        sgemm_kernel<1><<<dim3(4, R_N / 128), 256>>>(p_hn, W1 + l * HID * WIDE * HID,
                                                     b1 + l * WIDE * HID, nullptr, p_buf1,
                                                     R_N, WIDE * HID, HID);
        sgemm_kernel<2><<<dim3(1, R_N / 128), 256>>>(p_buf1, W2 + l * WIDE * HID * HID,
                                                     b2 + l * HID, p_h, p_h,
                                                     R_N, HID, WIDE * HID);
        readout_kernel<<<R_N / 16, 160>>>(p_h, Wro + l * HID * 9, bro + l * 9, p_readout);
    }

    // zero the FULL output (704 floats) before atomics accumulate into it
    int out_elems = NBATCH * OUT_S + NBATCH * 3;
    zero_kernel<<<(out_elems + 255) / 256, 256>>>(out, out_elems);
    finalize_kernel<<<(N_NODES + 255) / 256, 256>>>(batch, out);
}